// round 3
// baseline (speedup 1.0000x reference)
#include <cuda_runtime.h>
#include <math.h>

// ---------------- problem constants ----------------
#define BB   32          // batch
#define TT   4096        // time steps
#define AD   128         // input feature dim
#define SS   100         // DP states
#define BDM  10          // bottleneck dim
#define HH   50          // LSTM hidden
#define DD   30          // head dim

// ---------------- global scratch (no allocs allowed) ----------------
__device__ float g_sims[(size_t)BB * TT * SS + 128];  // allsims, padded
__device__ float g_z[(size_t)BB * TT * BDM];          // z (post 3-layer MLP)

// =====================================================================
// Kernel 1: z = mlp(x);  allsims = z @ c      (fully parallel)
// one thread per (b,t)
// =====================================================================
__global__ void k_project(const float* __restrict__ x, const float* __restrict__ c,
                          const float* __restrict__ w1, const float* __restrict__ b1,
                          const float* __restrict__ w2, const float* __restrict__ b2,
                          const float* __restrict__ w3, const float* __restrict__ b3)
{
    __shared__ float w1s[BDM * AD];    // 10x128
    __shared__ float cs[BDM * SS];     // 10x100
    __shared__ float w2s[BDM * BDM], w3s[BDM * BDM];
    __shared__ float b1s[BDM], b2s[BDM], b3s[BDM];

    int tid = threadIdx.x;
    for (int i = tid; i < BDM * AD; i += 256) w1s[i] = w1[i];
    for (int i = tid; i < BDM * SS; i += 256) cs[i] = c[i];
    if (tid < BDM * BDM) { w2s[tid] = w2[tid]; w3s[tid] = w3[tid]; }
    if (tid < BDM) { b1s[tid] = b1[tid]; b2s[tid] = b2[tid]; b3s[tid] = b3[tid]; }
    __syncthreads();

    int gtid = blockIdx.x * 256 + tid;             // (b*T + t), exact grid
    const float4* xr = (const float4*)(x + (size_t)gtid * AD);

    float z1[BDM];
#pragma unroll
    for (int d = 0; d < BDM; d++) z1[d] = b1s[d];

#pragma unroll 8
    for (int kk = 0; kk < AD / 4; ++kk) {
        float4 xv = xr[kk];
#pragma unroll
        for (int d = 0; d < BDM; d++) {
            float4 wv = ((const float4*)w1s)[d * (AD / 4) + kk];
            z1[d] += xv.x * wv.x + xv.y * wv.y + xv.z * wv.z + xv.w * wv.w;
        }
    }
#pragma unroll
    for (int d = 0; d < BDM; d++) z1[d] = fmaxf(z1[d], 0.0f);

    float z2[BDM];
#pragma unroll
    for (int d = 0; d < BDM; d++) {
        float a = b2s[d];
#pragma unroll
        for (int e = 0; e < BDM; e++) a += z1[e] * w2s[d * BDM + e];
        z2[d] = fmaxf(a, 0.0f);
    }
    float z3[BDM];
#pragma unroll
    for (int d = 0; d < BDM; d++) {
        float a = b3s[d];
#pragma unroll
        for (int e = 0; e < BDM; e++) a += z2[e] * w3s[d * BDM + e];
        z3[d] = a;
    }

    float* zo = g_z + (size_t)gtid * BDM;
#pragma unroll
    for (int d = 0; d < BDM; d++) zo[d] = z3[d];

    float* so = g_sims + (size_t)gtid * SS;
#pragma unroll
    for (int sq = 0; sq < SS / 4; ++sq) {
        float4 a = make_float4(0.f, 0.f, 0.f, 0.f);
#pragma unroll
        for (int d = 0; d < BDM; d++) {
            float4 cv = ((const float4*)cs)[d * (SS / 4) + sq];
            a.x += z3[d] * cv.x; a.y += z3[d] * cv.y;
            a.z += z3[d] * cv.z; a.w += z3[d] * cv.w;
        }
        ((float4*)so)[sq] = a;
    }
}

// =====================================================================
// Kernel 2: per-b: DP forward (warp 0) -> backtrack -> segment mean ->
//           LSTM -> MLP head.  One block per b, 128 threads.
// =====================================================================
struct SmemB {
    unsigned int bts[512 * 32];   // 64KB: backtrack bits, [(idx>>3)*32 + lane], 4 bits/lane/step
    float wih[4 * HH * BDM];      // 200x10
    float whh[4 * HH * HH];       // 200x50
    float bsum[4 * HH];           // b_ih + b_hh
    float wr1[DD * HH];           // 30x50
    float wr2[DD * DD];           // 30x30
    float br1[32];
    float br2[32];
    float wr3[32];
    float br3v;
    float zz[SS * BDM];           // segment sums -> means
    float cnt[SS];
    float hbuf[HH], cbuf[HH], gates[4 * HH];
    float rbuf[32], r2buf[32];
    unsigned char states[TT];
};

__device__ __forceinline__ float sigm(float v) { return 1.0f / (1.0f + __expf(-v)); }

__global__ void k_dp(const float* __restrict__ w_ih, const float* __restrict__ w_hh,
                     const float* __restrict__ b_ih, const float* __restrict__ b_hh,
                     const float* __restrict__ wr1, const float* __restrict__ br1,
                     const float* __restrict__ wr2, const float* __restrict__ br2,
                     const float* __restrict__ wr3, const float* __restrict__ br3,
                     float* __restrict__ out)
{
    extern __shared__ unsigned char smraw[];
    SmemB* sm = reinterpret_cast<SmemB*>(smraw);

    const int tid = threadIdx.x;
    const int b = blockIdx.x;

    // ---- cooperative weight staging + zero init ----
    for (int i = tid; i < 4 * HH * BDM; i += 128) sm->wih[i] = w_ih[i];
    for (int i = tid; i < 4 * HH * HH; i += 128) sm->whh[i] = w_hh[i];
    for (int i = tid; i < 4 * HH; i += 128) sm->bsum[i] = b_ih[i] + b_hh[i];
    for (int i = tid; i < DD * HH; i += 128) sm->wr1[i] = wr1[i];
    for (int i = tid; i < DD * DD; i += 128) sm->wr2[i] = wr2[i];
    if (tid < DD) { sm->br1[tid] = br1[tid]; sm->br2[tid] = br2[tid]; sm->wr3[tid] = wr3[tid]; }
    if (tid == 0) sm->br3v = br3[0];
    for (int i = tid; i < SS * BDM; i += 128) sm->zz[i] = 0.0f;
    for (int i = tid; i < SS; i += 128) sm->cnt[i] = 0.0f;
    if (tid < HH) { sm->hbuf[tid] = 0.0f; sm->cbuf[tid] = 0.0f; }
    __syncthreads();

    // ---- DP forward: warp 0 only; lane owns states 4L..4L+3 ----
    if (tid < 32) {
        const int lane = tid;
        const float* base = g_sims + (size_t)b * TT * SS + 4 * lane;

        float4 v0 = *(const float4*)(base);               // t = 0
        float st0 = v0.x, st1 = v0.y, st2 = v0.z, st3 = v0.w;

        float4 pf[8];
#pragma unroll
        for (int p = 0; p < 8; p++) pf[p] = *(const float4*)(base + (size_t)(1 + p) * SS);

        unsigned acc = 0;
        for (int g = 0; g < 511; ++g) {
#pragma unroll
            for (int p = 0; p < 8; p++) {
                int t = g * 8 + 1 + p;
                float4 sv = pf[p];
                pf[p] = *(const float4*)(base + (size_t)(t + 8) * SS);  // prefetch (in-bounds via pad)

                float left = __shfl_up_sync(0xffffffffu, st3, 1);
                if (lane == 0) left = 0.0f;                 // jnp.pad with 0

                unsigned bb = (unsigned)(left > st0) | ((unsigned)(st0 > st1) << 1)
                            | ((unsigned)(st1 > st2) << 2) | ((unsigned)(st2 > st3) << 3);
                float n0 = fmaxf(left, st0) + sv.x;
                float n1 = fmaxf(st0, st1) + sv.y;
                float n2 = fmaxf(st1, st2) + sv.z;
                float n3 = fmaxf(st2, st3) + sv.w;
                acc |= bb << (p * 4);
                st0 = n0; st1 = n1; st2 = n2; st3 = n3;
            }
            sm->bts[g * 32 + lane] = acc;
            acc = 0;
        }
        // tail: t = 4089..4095 (7 steps)
#pragma unroll
        for (int p = 0; p < 7; p++) {
            int t = 4089 + p;
            float4 sv = *(const float4*)(base + (size_t)t * SS);
            float left = __shfl_up_sync(0xffffffffu, st3, 1);
            if (lane == 0) left = 0.0f;
            unsigned bb = (unsigned)(left > st0) | ((unsigned)(st0 > st1) << 1)
                        | ((unsigned)(st1 > st2) << 2) | ((unsigned)(st2 > st3) << 3);
            float n0 = fmaxf(left, st0) + sv.x;
            float n1 = fmaxf(st0, st1) + sv.y;
            float n2 = fmaxf(st1, st2) + sv.z;
            float n3 = fmaxf(st2, st3) + sv.w;
            acc |= bb << (p * 4);
            st0 = n0; st1 = n1; st2 = n2; st3 = n3;
        }
        sm->bts[511 * 32 + lane] = acc;
    }
    __syncthreads();

    // ---- backtrack (serial on thread 0); mask (state >= t) applied here ----
    if (tid == 0) {
        int s = SS - 1;
        sm->states[TT - 1] = (unsigned char)s;
        for (int tt = TT - 1; tt >= 1; --tt) {
            int bit;
            if (s >= tt) {
                bit = 1;
            } else {
                int idx = tt - 1;
                unsigned w = sm->bts[(idx >> 3) * 32 + (s >> 2)];
                bit = (int)((w >> (((idx & 7) << 2) + (s & 3))) & 1u);
            }
            s -= bit;
            sm->states[tt - 1] = (unsigned char)s;
        }
    }
    __syncthreads();

    // ---- segment sums: each thread handles 32 consecutive t, run-length local accumulate ----
    {
        const int t0 = tid * 32;
        const float* zb = g_z + ((size_t)b * TT + t0) * BDM;
        float accv[BDM];
        float ca = 0.0f;
        int scur = sm->states[t0];
#pragma unroll
        for (int d = 0; d < BDM; d++) accv[d] = 0.0f;

        for (int k = 0; k < 32; ++k) {
            int sv = sm->states[t0 + k];
            if (sv != scur) {
#pragma unroll
                for (int d = 0; d < BDM; d++) atomicAdd(&sm->zz[scur * BDM + d], accv[d]);
                atomicAdd(&sm->cnt[scur], ca);
                scur = sv; ca = 0.0f;
#pragma unroll
                for (int d = 0; d < BDM; d++) accv[d] = 0.0f;
            }
#pragma unroll
            for (int d = 0; d < BDM; d++) accv[d] += zb[k * BDM + d];
            ca += 1.0f;
        }
#pragma unroll
        for (int d = 0; d < BDM; d++) atomicAdd(&sm->zz[scur * BDM + d], accv[d]);
        atomicAdd(&sm->cnt[scur], ca);
    }
    __syncthreads();

    // mean (path visits every state 0..99 exactly once or more => cnt >= 1)
    for (int i = tid; i < SS * BDM; i += 128) sm->zz[i] = sm->zz[i] / sm->cnt[i / BDM];
    __syncthreads();

    // ---- LSTM over S=100 steps ----
    for (int stp = 0; stp < SS; ++stp) {
        for (int j = tid; j < 4 * HH; j += 128) {
            float g = sm->bsum[j];
            const float* xt = sm->zz + stp * BDM;
            const float* wi = sm->wih + j * BDM;
#pragma unroll
            for (int d = 0; d < BDM; d++) g += wi[d] * xt[d];
            const float* wh = sm->whh + j * HH;
#pragma unroll 10
            for (int k = 0; k < HH; k++) g += wh[k] * sm->hbuf[k];
            sm->gates[j] = g;
        }
        __syncthreads();
        if (tid < HH) {
            float iv = sm->gates[tid];
            float fv = sm->gates[HH + tid];
            float gv = sm->gates[2 * HH + tid];
            float ov = sm->gates[3 * HH + tid];
            float cc = sigm(fv) * sm->cbuf[tid] + sigm(iv) * tanhf(gv);
            sm->cbuf[tid] = cc;
            sm->hbuf[tid] = sigm(ov) * tanhf(cc);
        }
        __syncthreads();
    }

    // ---- MLP head ----
    if (tid < DD) {
        float r = sm->br1[tid];
#pragma unroll 10
        for (int k = 0; k < HH; k++) r += sm->wr1[tid * HH + k] * sm->hbuf[k];
        sm->rbuf[tid] = fmaxf(r, 0.0f);
    }
    __syncthreads();
    if (tid < DD) {
        float r = sm->br2[tid];
#pragma unroll
        for (int k = 0; k < DD; k++) r += sm->wr2[tid * DD + k] * sm->rbuf[k];
        sm->r2buf[tid] = fmaxf(r, 0.0f);
    }
    __syncthreads();
    if (tid == 0) {
        float r = sm->br3v;
#pragma unroll
        for (int d = 0; d < DD; d++) r += sm->wr3[d] * sm->r2buf[d];
        out[b] = r;
    }
}

// =====================================================================
// launch
// =====================================================================
extern "C" void kernel_launch(void* const* d_in, const int* in_sizes, int n_in,
                              void* d_out, int out_size)
{
    (void)in_sizes; (void)n_in; (void)out_size;
    const float* x    = (const float*)d_in[0];
    const float* c    = (const float*)d_in[1];
    const float* w1   = (const float*)d_in[2];
    const float* b1   = (const float*)d_in[3];
    const float* w2   = (const float*)d_in[4];
    const float* b2   = (const float*)d_in[5];
    const float* w3   = (const float*)d_in[6];
    const float* b3   = (const float*)d_in[7];
    const float* w_ih = (const float*)d_in[8];
    const float* w_hh = (const float*)d_in[9];
    const float* b_ih = (const float*)d_in[10];
    const float* b_hh = (const float*)d_in[11];
    const float* wr1  = (const float*)d_in[12];
    const float* br1  = (const float*)d_in[13];
    const float* wr2  = (const float*)d_in[14];
    const float* br2  = (const float*)d_in[15];
    const float* wr3  = (const float*)d_in[16];
    const float* br3  = (const float*)d_in[17];
    float* out = (float*)d_out;

    cudaFuncSetAttribute(k_dp, cudaFuncAttributeMaxDynamicSharedMemorySize,
                         (int)sizeof(SmemB));

    k_project<<<(BB * TT) / 256, 256>>>(x, c, w1, b1, w2, b2, w3, b3);
    k_dp<<<BB, 128, sizeof(SmemB)>>>(w_ih, w_hh, b_ih, b_hh,
                                     wr1, br1, wr2, br2, wr3, br3, out);
}

// round 4
// speedup vs baseline: 2.2516x; 2.2516x over previous
#include <cuda_runtime.h>
#include <math.h>

// ---------------- problem constants ----------------
#define BB   32          // batch
#define TT   4096        // time steps
#define AD   128         // input feature dim
#define SS   100         // DP states
#define BDM  10          // bottleneck dim
#define HH   50          // LSTM hidden
#define DD   30          // head dim
#define CH   64          // DP chunk (timesteps per smem tile)
#define NCH  (TT / CH)   // 64 chunks

// ---------------- global scratch ----------------
__device__ __align__(16) float g_sims[(size_t)BB * TT * SS + 128];
__device__ __align__(16) float g_z[(size_t)BB * TT * BDM];

// =====================================================================
// Kernel 1: z = mlp(x);  allsims = z @ c      (fully parallel)
// =====================================================================
__global__ void k_project(const float* __restrict__ x, const float* __restrict__ c,
                          const float* __restrict__ w1, const float* __restrict__ b1,
                          const float* __restrict__ w2, const float* __restrict__ b2,
                          const float* __restrict__ w3, const float* __restrict__ b3)
{
    __shared__ float w1s[BDM * AD];
    __shared__ float cs[BDM * SS];
    __shared__ float w2s[BDM * BDM], w3s[BDM * BDM];
    __shared__ float b1s[BDM], b2s[BDM], b3s[BDM];

    int tid = threadIdx.x;
    for (int i = tid; i < BDM * AD; i += 256) w1s[i] = w1[i];
    for (int i = tid; i < BDM * SS; i += 256) cs[i] = c[i];
    if (tid < BDM * BDM) { w2s[tid] = w2[tid]; w3s[tid] = w3[tid]; }
    if (tid < BDM) { b1s[tid] = b1[tid]; b2s[tid] = b2[tid]; b3s[tid] = b3[tid]; }
    __syncthreads();

    int gtid = blockIdx.x * 256 + tid;
    const float4* xr = (const float4*)(x + (size_t)gtid * AD);

    float z1[BDM];
#pragma unroll
    for (int d = 0; d < BDM; d++) z1[d] = b1s[d];

#pragma unroll 8
    for (int kk = 0; kk < AD / 4; ++kk) {
        float4 xv = xr[kk];
#pragma unroll
        for (int d = 0; d < BDM; d++) {
            float4 wv = ((const float4*)w1s)[d * (AD / 4) + kk];
            z1[d] += xv.x * wv.x + xv.y * wv.y + xv.z * wv.z + xv.w * wv.w;
        }
    }
#pragma unroll
    for (int d = 0; d < BDM; d++) z1[d] = fmaxf(z1[d], 0.0f);

    float z2[BDM];
#pragma unroll
    for (int d = 0; d < BDM; d++) {
        float a = b2s[d];
#pragma unroll
        for (int e = 0; e < BDM; e++) a += z1[e] * w2s[d * BDM + e];
        z2[d] = fmaxf(a, 0.0f);
    }
    float z3[BDM];
#pragma unroll
    for (int d = 0; d < BDM; d++) {
        float a = b3s[d];
#pragma unroll
        for (int e = 0; e < BDM; e++) a += z2[e] * w3s[d * BDM + e];
        z3[d] = a;
    }

    float* zo = g_z + (size_t)gtid * BDM;
#pragma unroll
    for (int d = 0; d < BDM; d++) zo[d] = z3[d];

    float* so = g_sims + (size_t)gtid * SS;
#pragma unroll
    for (int sq = 0; sq < SS / 4; ++sq) {
        float4 a = make_float4(0.f, 0.f, 0.f, 0.f);
#pragma unroll
        for (int d = 0; d < BDM; d++) {
            float4 cv = ((const float4*)cs)[d * (SS / 4) + sq];
            a.x += z3[d] * cv.x; a.y += z3[d] * cv.y;
            a.z += z3[d] * cv.z; a.w += z3[d] * cv.w;
        }
        ((float4*)so)[sq] = a;
    }
}

// =====================================================================
// Kernel 2: pipelined DP + fast backtrack + segment mean + LSTM + head.
// One block per b, 256 threads (warp0 = DP consumer, warps 1-7 = loaders).
// Backtrack bit for forward step t lives at word (t>>3), nibble (t&7),
// bit (state&3) of column (state>>2).
// =====================================================================
struct SmemB {
    float simbuf[2][CH * SS];     // 51.2 KB double buffer
    unsigned int bts[512 * 32];   // 64 KB backtrack bits
    int bound[SS + 4];            // segment boundaries
    float zz[SS * BDM];
    float hbuf[HH], cbuf[HH], gates[4 * HH];
    float rbuf[32], r2buf[32];
};

__device__ __forceinline__ float sigm(float v) { return 1.0f / (1.0f + __expf(-v)); }

#define DPSTEP(sv, nib) do {                                                     \
    float left = __shfl_up_sync(0xffffffffu, st3, 1);                            \
    if (lane == 0) left = 0.0f;                                                  \
    unsigned bbit = (unsigned)(left > st0) | ((unsigned)(st0 > st1) << 1)        \
                  | ((unsigned)(st1 > st2) << 2) | ((unsigned)(st2 > st3) << 3); \
    acc |= bbit << ((nib) * 4);                                                  \
    float n0 = fmaxf(left, st0) + (sv).x;                                        \
    float n1 = fmaxf(st0, st1) + (sv).y;                                         \
    float n2 = fmaxf(st1, st2) + (sv).z;                                         \
    float n3 = fmaxf(st2, st3) + (sv).w;                                         \
    st0 = n0; st1 = n1; st2 = n2; st3 = n3; } while (0)

__global__ void __launch_bounds__(256, 1)
k_dp(const float* __restrict__ w_ih, const float* __restrict__ w_hh,
     const float* __restrict__ b_ih, const float* __restrict__ b_hh,
     const float* __restrict__ wr1, const float* __restrict__ br1,
     const float* __restrict__ wr2, const float* __restrict__ br2,
     const float* __restrict__ wr3, const float* __restrict__ br3,
     float* __restrict__ out)
{
    extern __shared__ unsigned char smraw[];
    SmemB* sm = reinterpret_cast<SmemB*>(smraw);

    const int tid = threadIdx.x;
    const int b = blockIdx.x;
    const float* simb = g_sims + (size_t)b * TT * SS;

    for (int i = tid; i < SS * BDM; i += 256) sm->zz[i] = 0.0f;
    if (tid < HH) { sm->hbuf[tid] = 0.0f; sm->cbuf[tid] = 0.0f; }

    // preload chunk 0 (all threads)
    for (int i = tid; i < CH * SS / 4; i += 256)
        ((float4*)sm->simbuf[0])[i] = ((const float4*)simb)[i];
    __syncthreads();

    // ================= pipelined DP forward =================
    float st0 = 0.f, st1 = 0.f, st2 = 0.f, st3 = 0.f;
    unsigned acc = 0;
    const int lane = tid & 31;

    for (int ci = 0; ci < NCH; ci++) {
        if (tid >= 32) {
            int cn = ci + 1;
            if (cn < NCH) {
                const float4* src = (const float4*)(simb + (size_t)cn * CH * SS);
                float4* dst = (float4*)sm->simbuf[cn & 1];
                for (int i = tid - 32; i < CH * SS / 4; i += 224) dst[i] = src[i];
            }
        } else {
            const float* sb = sm->simbuf[ci & 1] + 4 * lane;
            if (ci == 0) {
                float4 v0 = *(const float4*)sb;
                st0 = v0.x; st1 = v0.y; st2 = v0.z; st3 = v0.w;
                acc = 0;
                float4 nxt = *(const float4*)(sb + 1 * SS);
#pragma unroll
                for (int r = 1; r < 8; r++) {
                    float4 sv = nxt;
                    nxt = *(const float4*)(sb + (r + 1) * SS);
                    DPSTEP(sv, r);
                }
                sm->bts[0 * 32 + lane] = acc;
                for (int gg = 1; gg < 8; gg++) {
                    acc = 0;
#pragma unroll
                    for (int p = 0; p < 8; p++) {
                        int r = gg * 8 + p;
                        float4 sv = nxt;
                        int rn = (r + 1 < CH) ? r + 1 : r;
                        nxt = *(const float4*)(sb + rn * SS);
                        DPSTEP(sv, p);
                    }
                    sm->bts[gg * 32 + lane] = acc;
                }
            } else {
                float4 nxt = *(const float4*)sb;
                for (int gg = 0; gg < 8; gg++) {
                    acc = 0;
#pragma unroll
                    for (int p = 0; p < 8; p++) {
                        int r = gg * 8 + p;
                        float4 sv = nxt;
                        int rn = (r + 1 < CH) ? r + 1 : r;
                        nxt = *(const float4*)(sb + rn * SS);
                        DPSTEP(sv, p);
                    }
                    sm->bts[(ci * 8 + gg) * 32 + lane] = acc;
                }
            }
        }
        __syncthreads();
    }

    // ================= warp-parallel backtrack =================
    // Effective bit at step tt for state s: stored OR forced (s >= tt).
    // Segment s = [tt_dec, cur]; tt_dec = max(prev stored set bit <= cur, s).
    if (tid < 32) {
        int s = SS - 1, cur = TT - 1;
        while (s > 0) {
            int col = s >> 2, sub = s & 3;
            unsigned msk = 0x11111111u << sub;
            int gtop = cur >> 3;
            int ttstar = 0;
            for (int gb = gtop - 31; ; gb -= 32) {
                int g = gb + lane;
                unsigned w = 0;
                if (g >= 0 && g <= gtop) {
                    w = sm->bts[g * 32 + col] & msk;
                    if (g == gtop) {
                        int pm = cur & 7;
                        if (pm < 7) w &= (1u << ((pm + 1) * 4)) - 1u;
                    }
                }
                unsigned bal = __ballot_sync(0xffffffffu, w != 0);
                if (bal) {
                    int hl = 31 - __clz((int)bal);
                    unsigned wh = __shfl_sync(0xffffffffu, w, hl);
                    int hb = 31 - __clz((int)wh);
                    ttstar = (gb + hl) * 8 + (hb >> 2);
                    break;
                }
                if (gb <= 0 || gb * 8 <= s + 1) break;
            }
            int ttd = ttstar > s ? ttstar : s;
            if (lane == 0) sm->bound[s] = ttd;
            cur = ttd - 1;
            s--;
        }
        if (lane == 0) { sm->bound[0] = 0; sm->bound[SS] = TT; }
    }
    __syncthreads();

    // ================= segment sums (256 threads x 16 t) =================
    {
        const int t0 = tid * (TT / 256);
        int lo = 0, hi = SS - 1;
        while (lo < hi) {
            int mid = (lo + hi + 1) >> 1;
            if (sm->bound[mid] <= t0) lo = mid; else hi = mid - 1;
        }
        int s = lo;
        int nxtb = sm->bound[s + 1];
        const float* zb = g_z + ((size_t)b * TT + t0) * BDM;
        float av[BDM];
#pragma unroll
        for (int d = 0; d < BDM; d++) av[d] = 0.0f;

        for (int k = 0; k < TT / 256; ++k) {
            int t = t0 + k;
            if (t >= nxtb) {
#pragma unroll
                for (int d = 0; d < BDM; d++) {
                    atomicAdd(&sm->zz[s * BDM + d], av[d]);
                    av[d] = 0.0f;
                }
                s++;
                nxtb = sm->bound[s + 1];
            }
#pragma unroll
            for (int d = 0; d < BDM; d++) av[d] += zb[k * BDM + d];
        }
#pragma unroll
        for (int d = 0; d < BDM; d++) atomicAdd(&sm->zz[s * BDM + d], av[d]);
    }
    __syncthreads();

    for (int i = tid; i < SS * BDM; i += 256) {
        int s = i / BDM;
        sm->zz[i] = sm->zz[i] / (float)(sm->bound[s + 1] - sm->bound[s]);
    }
    __syncthreads();

    // ================= LSTM (weights in registers) =================
    float whr[HH], wir[BDM], bsr = 0.0f;
    if (tid < 4 * HH) {
#pragma unroll
        for (int k = 0; k < HH; k++) whr[k] = w_hh[tid * HH + k];
#pragma unroll
        for (int d = 0; d < BDM; d++) wir[d] = w_ih[tid * BDM + d];
        bsr = b_ih[tid] + b_hh[tid];
    }

    for (int stp = 0; stp < SS; ++stp) {
        if (tid < 4 * HH) {
            float g = bsr;
            const float* xt = sm->zz + stp * BDM;
#pragma unroll
            for (int d = 0; d < BDM; d++) g += wir[d] * xt[d];
#pragma unroll
            for (int k = 0; k < HH; k++) g += whr[k] * sm->hbuf[k];
            sm->gates[tid] = g;
        }
        __syncthreads();
        if (tid < HH) {
            float iv = sm->gates[tid];
            float fv = sm->gates[HH + tid];
            float gv = sm->gates[2 * HH + tid];
            float ov = sm->gates[3 * HH + tid];
            float cc = sigm(fv) * sm->cbuf[tid] + sigm(iv) * tanhf(gv);
            sm->cbuf[tid] = cc;
            sm->hbuf[tid] = sigm(ov) * tanhf(cc);
        }
        __syncthreads();
    }

    // ================= MLP head =================
    if (tid < DD) {
        float r = br1[tid];
#pragma unroll 10
        for (int k = 0; k < HH; k++) r += wr1[tid * HH + k] * sm->hbuf[k];
        sm->rbuf[tid] = fmaxf(r, 0.0f);
    }
    __syncthreads();
    if (tid < DD) {
        float r = br2[tid];
#pragma unroll
        for (int k = 0; k < DD; k++) r += wr2[tid * DD + k] * sm->rbuf[k];
        sm->r2buf[tid] = fmaxf(r, 0.0f);
    }
    __syncthreads();
    if (tid == 0) {
        float r = br3[0];
#pragma unroll
        for (int d = 0; d < DD; d++) r += wr3[d] * sm->r2buf[d];
        out[b] = r;
    }
}

// =====================================================================
// launch
// =====================================================================
extern "C" void kernel_launch(void* const* d_in, const int* in_sizes, int n_in,
                              void* d_out, int out_size)
{
    (void)in_sizes; (void)n_in; (void)out_size;
    const float* x    = (const float*)d_in[0];
    const float* c    = (const float*)d_in[1];
    const float* w1   = (const float*)d_in[2];
    const float* b1   = (const float*)d_in[3];
    const float* w2   = (const float*)d_in[4];
    const float* b2   = (const float*)d_in[5];
    const float* w3   = (const float*)d_in[6];
    const float* b3   = (const float*)d_in[7];
    const float* w_ih = (const float*)d_in[8];
    const float* w_hh = (const float*)d_in[9];
    const float* b_ih = (const float*)d_in[10];
    const float* b_hh = (const float*)d_in[11];
    const float* wr1  = (const float*)d_in[12];
    const float* br1  = (const float*)d_in[13];
    const float* wr2  = (const float*)d_in[14];
    const float* br2  = (const float*)d_in[15];
    const float* wr3  = (const float*)d_in[16];
    const float* br3  = (const float*)d_in[17];
    float* out = (float*)d_out;

    cudaFuncSetAttribute(k_dp, cudaFuncAttributeMaxDynamicSharedMemorySize,
                         (int)sizeof(SmemB));

    k_project<<<(BB * TT) / 256, 256>>>(x, c, w1, b1, w2, b2, w3, b3);
    k_dp<<<BB, 256, sizeof(SmemB)>>>(w_ih, w_hh, b_ih, b_hh,
                                     wr1, br1, wr2, br2, wr3, br3, out);
}